// round 17
// baseline (speedup 1.0000x reference)
#include <cuda_runtime.h>
#include <cuda_bf16.h>
#include <cstdint>

#define D     256
#define NB    30
#define EG    240
#define BG    2048
#define GAUX  8
#define H32ST 260     // fp32 row stride (1040B, 16B-aligned)
#define AST   520     // bf16 row stride (1040B)

// fused fp32x2 FMA
#define FMA2(d, a, b) \
    asm("fma.rn.f32x2 %0, %1, %2, %0;" : "+l"(d) : "l"(a), "l"(b))
// m16n8k16 bf16 mma
#define MMA16816(d, a, b0_, b1_) \
    asm volatile("mma.sync.aligned.m16n8k16.row.col.f32.bf16.bf16.f32 " \
                 "{%0,%1,%2,%3}, {%4,%5,%6,%7}, {%8,%9}, {%0,%1,%2,%3};" \
                 : "+f"((d)[0]), "+f"((d)[1]), "+f"((d)[2]), "+f"((d)[3]) \
                 : "r"((a)[0]), "r"((a)[1]), "r"((a)[2]), "r"((a)[3]), \
                   "r"(b0_), "r"(b1_))

__device__ __forceinline__ unsigned short bfhi(float x) {
    return __bfloat16_as_ushort(__float2bfloat16_rn(x));
}
__device__ __forceinline__ unsigned short bflo(float x) {
    float h = __bfloat162float(__float2bfloat16_rn(x));
    return __bfloat16_as_ushort(__float2bfloat16_rn(x - h));
}

__device__ float g_Mgeo[5 * D];
__device__ float g_Msem[11 * D];
__device__ float g_bias0[D];
__device__ float g_gbuf[BG * 4 * D];
// FFMA2 weights (cols 0..127): [l][kp2(256)][cp(64)] = {(k0,k1)@2cp, (k0,k1)@2cp+1}
__device__ ulonglong2 g_Wp2[3][256 * 64];
// mma B fragments (cols 128..255): id = (((l*2+p)*32+ks)*16+nt)*32+lane
__device__ unsigned long long g_Bfrag[3 * 2 * 32 * 16 * 32];

// dynamic smem offsets (bytes)
#define OFF_H32  0
#define OFF_XA32 33280
#define OFF_AHI  66560
#define OFF_ALO  99840
#define DYN_SZ   133120

// ---------------------------------------------------------------------------
__global__ void init_kernel(const float* __restrict__ Wgeo,
                            const float* __restrict__ bgeo,
                            const float* __restrict__ emb,
                            const float* __restrict__ Wlot,
                            const float* __restrict__ blot,
                            const float* __restrict__ W1,
                            const float* __restrict__ W2,
                            const float* __restrict__ W3)
{
    int b = blockIdx.x;
    if (b < 17) {
        int c = threadIdx.x;
        int r = b;
        float a0 = 0.f, a1 = 0.f, a2 = 0.f, a3 = 0.f;
        if (r < 5) {
            for (int j = 0; j < D; j += 4) {
                a0 = fmaf(Wgeo[r * D + j + 0], Wlot[(j + 0) * D + c], a0);
                a1 = fmaf(Wgeo[r * D + j + 1], Wlot[(j + 1) * D + c], a1);
                a2 = fmaf(Wgeo[r * D + j + 2], Wlot[(j + 2) * D + c], a2);
                a3 = fmaf(Wgeo[r * D + j + 3], Wlot[(j + 3) * D + c], a3);
            }
            g_Mgeo[r * D + c] = (a0 + a1) + (a2 + a3);
        } else if (r < 16) {
            int s = r - 5;
            for (int j = 0; j < D; j += 4) {
                a0 = fmaf(emb[s * D + j + 0], Wlot[(D + j + 0) * D + c], a0);
                a1 = fmaf(emb[s * D + j + 1], Wlot[(D + j + 1) * D + c], a1);
                a2 = fmaf(emb[s * D + j + 2], Wlot[(D + j + 2) * D + c], a2);
                a3 = fmaf(emb[s * D + j + 3], Wlot[(D + j + 3) * D + c], a3);
            }
            g_Msem[s * D + c] = (a0 + a1) + (a2 + a3);
        } else {
            for (int j = 0; j < D; j += 4) {
                a0 = fmaf(bgeo[j + 0], Wlot[(j + 0) * D + c], a0);
                a1 = fmaf(bgeo[j + 1], Wlot[(j + 1) * D + c], a1);
                a2 = fmaf(bgeo[j + 2], Wlot[(j + 2) * D + c], a2);
                a3 = fmaf(bgeo[j + 3], Wlot[(j + 3) * D + c], a3);
            }
            g_bias0[c] = blot[c] + (a0 + a1) + (a2 + a3);
        }
        return;
    }
    if (b < 17 + 384) {
        // mma B fragments, cols 128..255
        int id = (b - 17) * 256 + threadIdx.x;      // < 98304
        int lane = id & 31;
        int nt = (id >> 5) & 15;
        int ks = (id >> 9) & 31;
        int p  = (id >> 14) & 1;
        int l  = id >> 15;
        if (l >= 3) return;
        const float* W = (l == 0) ? W1 : (l == 1) ? W2 : W3;
        int gq = lane >> 2, lq = lane & 3;
        int n  = 128 + nt * 8 + gq;
        int k0 = ks * 16 + 2 * lq;
        float v00 = W[(k0 + 0) * D + n], v01 = W[(k0 + 1) * D + n];
        float v10 = W[(k0 + 8) * D + n], v11 = W[(k0 + 9) * D + n];
        unsigned short s00, s01, s10, s11;
        if (p == 0) { s00 = bfhi(v00); s01 = bfhi(v01); s10 = bfhi(v10); s11 = bfhi(v11); }
        else        { s00 = bflo(v00); s01 = bflo(v01); s10 = bflo(v10); s11 = bflo(v11); }
        unsigned int b0 = ((unsigned int)s01 << 16) | s00;
        unsigned int b1 = ((unsigned int)s11 << 16) | s10;
        g_Bfrag[id] = ((unsigned long long)b1 << 32) | b0;
        return;
    }
    // FFMA2 weights, cols 0..127 (fp32 K-pair/col-pair pack)
    int id = (b - 17 - 384) * 256 + threadIdx.x;    // < 49152
    int cp  = id & 63;
    int kp2 = (id >> 6) & 255;
    int l   = id >> 14;
    if (l >= 3) return;
    const float* W = (l == 0) ? W1 : (l == 1) ? W2 : W3;
    int k0 = 2 * kp2;
    int c0 = 2 * cp;
    unsigned lo0 = __float_as_uint(W[k0 * D + c0]);
    unsigned hi0 = __float_as_uint(W[(k0 + 1) * D + c0]);
    unsigned lo1 = __float_as_uint(W[k0 * D + c0 + 1]);
    unsigned hi1 = __float_as_uint(W[(k0 + 1) * D + c0 + 1]);
    ulonglong2 v;
    v.x = (unsigned long long)lo0 | ((unsigned long long)hi0 << 32);
    v.y = (unsigned long long)lo1 | ((unsigned long long)hi1 << 32);
    g_Wp2[l][kp2 * 64 + cp] = v;
}

// ---------------------------------------------------------------------------
// One CTA per graph, 256 threads. Pipe-split GEMM:
//   warps 0-3: mma.sync (tensor pipe), output cols 128..255, split-bf16 3-pass
//   warps 4-7: fma.rn.f32x2 (fma pipe), output cols 0..127, exact fp32
// Each SMSP carries one warp of each kind -> both pipes busy concurrently.
// ---------------------------------------------------------------------------
__global__ void __launch_bounds__(256, 1)
graph_kernel(const float* __restrict__ geometry,
             const int*   __restrict__ semantic,
             const int*   __restrict__ e_src,
             const int*   __restrict__ e_dst,
             const float* __restrict__ Wlot,
             const float* __restrict__ bmp1,
             const float* __restrict__ bmp2,
             const float* __restrict__ bmp3)
{
    extern __shared__ char dyn[];
    float* h32  = (float*)(dyn + OFF_H32);                 // [32][H32ST]
    float* xa32 = (float*)(dyn + OFF_XA32);                // [32][H32ST]
    __nv_bfloat16* Ahi = (__nv_bfloat16*)(dyn + OFF_AHI);  // [32][AST] = [h|xa]
    __nv_bfloat16* Alo = (__nv_bfloat16*)(dyn + OFF_ALO);

    __shared__ int   s_sem[32], s_cnt[32], s_off[33], s_cur[32], s_list[EG];
    __shared__ float s_inv[32], s_geo[150], s_bias[256];
    __shared__ unsigned int s_max[256];

    const int g    = blockIdx.x;
    const int tid  = threadIdx.x;
    const int wid  = tid >> 5;
    const int lane = tid & 31;
    const int gq   = lane >> 2;
    const int lq   = lane & 3;

    // ---- CSR ----
    for (int i = tid; i < NB * 5; i += 256) s_geo[i] = geometry[g * NB * 5 + i];
    if (tid < NB) { s_sem[tid] = semantic[g * NB + tid]; s_cnt[tid] = 0; }
    s_max[tid] = 0;
    __syncthreads();
    if (tid < EG) {
        int d = e_dst[g * EG + tid] - g * NB;
        atomicAdd(&s_cnt[d], 1);
    }
    __syncthreads();
    if (tid == 0) {
        int a = 0;
        for (int i = 0; i < NB; i++) { s_off[i] = a; s_cur[i] = a; a += s_cnt[i]; }
        s_off[NB] = a;
    }
    if (tid < NB) s_inv[tid] = s_cnt[tid] ? 1.0f / (float)s_cnt[tid] : 0.0f;
    __syncthreads();
    if (tid < EG) {
        int s = e_src[g * EG + tid] - g * NB;
        int d = e_dst[g * EG + tid] - g * NB;
        int p = atomicAdd(&s_cur[d], 1);
        s_list[p] = s;
    }

    // ---- h0: thread = column c ----
    {
        const int c = tid;
        float mg0 = g_Mgeo[c], mg1 = g_Mgeo[D + c], mg2 = g_Mgeo[2 * D + c];
        float mg3 = g_Mgeo[3 * D + c], mg4 = g_Mgeo[4 * D + c];
        const float bb = g_bias0[c];
        float cm = 0.f;
        for (int r = 0; r < 32; r++) {
            float v = 0.f;
            if (r < NB) {
                v = bb + Wlot[(2 * D + r) * D + c] + g_Msem[s_sem[r] * D + c];
                const float* ge = s_geo + r * 5;
                v = fmaf(ge[0], mg0, v); v = fmaf(ge[1], mg1, v);
                v = fmaf(ge[2], mg2, v); v = fmaf(ge[3], mg3, v);
                v = fmaf(ge[4], mg4, v);
                v = fmaxf(v, 0.f);
            }
            h32[r * H32ST + c] = v;
            Ahi[r * AST + c] = __ushort_as_bfloat16(bfhi(v));
            Alo[r * AST + c] = __ushort_as_bfloat16(bflo(v));
            cm = fmaxf(cm, v);
        }
        g_gbuf[g * 1024 + c] = cm;
    }
    __syncthreads();

    // ---- 3 layers ----
    for (int l = 0; l < 3; l++) {
        const float* bias = (l == 0) ? bmp1 : (l == 1) ? bmp2 : bmp3;
        s_bias[tid] = bias[tid];

        // gather: thread = column c
        {
            const int c = tid;
            for (int r = 0; r < 32; r++) {
                float x = 0.f;
                if (r < NB && s_cnt[r]) {
                    int e0 = s_off[r], e1 = s_off[r + 1];
                    for (int e = e0; e < e1; e++)
                        x += h32[s_list[e] * H32ST + c];
                    x *= s_inv[r];
                }
                xa32[r * H32ST + c] = x;
                Ahi[r * AST + D + c] = __ushort_as_bfloat16(bfhi(x));
                Alo[r * AST + D + c] = __ushort_as_bfloat16(bflo(x));
            }
        }
        __syncthreads();

        if (wid < 4) {
            // ======== mma.sync warps: cols 128 + [32w, 32w+32) ========
            float acc[2][4][4];
            #pragma unroll
            for (int mt = 0; mt < 2; mt++)
                #pragma unroll
                for (int j = 0; j < 4; j++)
                    #pragma unroll
                    for (int r = 0; r < 4; r++) acc[mt][j][r] = 0.f;

            #pragma unroll 1
            for (int pass = 0; pass < 3; pass++) {
                const __nv_bfloat16* Ap = (pass == 1) ? Alo : Ahi;
                const int bp = (pass == 2) ? 1 : 0;
                const unsigned long long* Bf =
                    g_Bfrag + ((size_t)(l * 2 + bp)) * 16384 + (wid * 4) * 32 + lane;
                unsigned long long bc[4];
                #pragma unroll
                for (int j = 0; j < 4; j++) bc[j] = Bf[j * 32];
                #pragma unroll 1
                for (int ks = 0; ks < 32; ks++) {
                    unsigned long long bn[4] = {0, 0, 0, 0};
                    if (ks < 31) {
                        #pragma unroll
                        for (int j = 0; j < 4; j++) bn[j] = Bf[(ks + 1) * 512 + j * 32];
                    }
                    const int kc = ks * 16 + 2 * lq;
                    uint32_t a[2][4];
                    #pragma unroll
                    for (int mt = 0; mt < 2; mt++) {
                        const __nv_bfloat16* Ar = Ap + (mt * 16 + gq) * AST + kc;
                        a[mt][0] = *(const uint32_t*)(Ar);
                        a[mt][1] = *(const uint32_t*)(Ar + 8 * AST);
                        a[mt][2] = *(const uint32_t*)(Ar + 8);
                        a[mt][3] = *(const uint32_t*)(Ar + 8 * AST + 8);
                    }
                    #pragma unroll
                    for (int mt = 0; mt < 2; mt++)
                        #pragma unroll
                        for (int j = 0; j < 4; j++) {
                            uint32_t b0 = (uint32_t)bc[j];
                            uint32_t b1 = (uint32_t)(bc[j] >> 32);
                            MMA16816(acc[mt][j], a[mt], b0, b1);
                        }
                    #pragma unroll
                    for (int j = 0; j < 4; j++) bc[j] = bn[j];
                }
            }
            __syncthreads();   // GEMM done (both halves)

            // epilogue (mma cols)
            #pragma unroll
            for (int nti = 0; nti < 4; nti++) {
                #pragma unroll
                for (int par = 0; par < 2; par++) {
                    const int col = 128 + wid * 32 + nti * 8 + 2 * lq + par;
                    const float bv = s_bias[col];
                    #pragma unroll
                    for (int mt = 0; mt < 2; mt++) {
                        #pragma unroll
                        for (int rh = 0; rh < 2; rh++) {
                            int row = mt * 16 + gq + rh * 8;
                            float v = acc[mt][nti][rh * 2 + par] + bv;
                            bool ok = (row < NB) && (s_cnt[row] != 0);
                            v = ok ? fmaxf(v, 0.f) : 0.f;
                            h32[row * H32ST + col] = v;
                            Ahi[row * AST + col] = __ushort_as_bfloat16(bfhi(v));
                            Alo[row * AST + col] = __ushort_as_bfloat16(bflo(v));
                            atomicMax(&s_max[col], __float_as_uint(v));
                        }
                    }
                }
            }
        } else {
            // ======== FFMA2 warps: cols 0..127 ========
            const int tt = tid - 128;          // 0..127
            const int cp = tt & 63;
            const int rg = tt >> 6;            // 0..1
            const int c0 = 2 * cp;
            const int r0 = rg * 16;

            unsigned long long acc[16][2];
            {
                float bx = s_bias[c0], by = s_bias[c0 + 1];
                #pragma unroll
                for (int i = 0; i < 16; i++) {
                    acc[i][0] = (unsigned long long)__float_as_uint(bx);
                    acc[i][1] = (unsigned long long)__float_as_uint(by);
                }
            }
            #pragma unroll
            for (int part = 0; part < 2; part++) {
                const float* A = (part ? xa32 : h32) + r0 * H32ST;
                const ulonglong2* Wb = g_Wp2[l] + part * 128 * 64 + cp;
                #pragma unroll 2
                for (int kpl = 0; kpl < 128; kpl += 2) {
                    ulonglong2 w0 = Wb[(kpl + 0) * 64];
                    ulonglong2 w1 = Wb[(kpl + 1) * 64];
                    const float* Ak = A + 2 * kpl;
                    #pragma unroll
                    for (int i = 0; i < 16; i++) {
                        ulonglong2 hv = *reinterpret_cast<const ulonglong2*>(Ak + i * H32ST);
                        FMA2(acc[i][0], hv.x, w0.x);
                        FMA2(acc[i][1], hv.x, w0.y);
                        FMA2(acc[i][0], hv.y, w1.x);
                        FMA2(acc[i][1], hv.y, w1.y);
                    }
                }
            }
            __syncthreads();   // GEMM done (both halves)

            // epilogue (FFMA2 cols)
            #pragma unroll
            for (int i = 0; i < 16; i++) {
                int n = r0 + i;
                float vx = 0.f, vy = 0.f;
                if (n < NB && s_cnt[n]) {
                    vx = fmaxf(__uint_as_float((unsigned)acc[i][0])
                             + __uint_as_float((unsigned)(acc[i][0] >> 32)), 0.f);
                    vy = fmaxf(__uint_as_float((unsigned)acc[i][1])
                             + __uint_as_float((unsigned)(acc[i][1] >> 32)), 0.f);
                }
                h32[n * H32ST + c0]     = vx;
                h32[n * H32ST + c0 + 1] = vy;
                Ahi[n * AST + c0]     = __ushort_as_bfloat16(bfhi(vx));
                Ahi[n * AST + c0 + 1] = __ushort_as_bfloat16(bfhi(vy));
                Alo[n * AST + c0]     = __ushort_as_bfloat16(bflo(vx));
                Alo[n * AST + c0 + 1] = __ushort_as_bfloat16(bflo(vy));
                atomicMax(&s_max[c0], __float_as_uint(vx));
                atomicMax(&s_max[c0 + 1], __float_as_uint(vy));
            }
        }
        __syncthreads();

        g_gbuf[g * 1024 + (l + 1) * D + tid] = __uint_as_float(s_max[tid]);
        s_max[tid] = 0;
        __syncthreads();
    }
}

// ---------------------------------------------------------------------------
__global__ void __launch_bounds__(256)
aux_kernel(const float* __restrict__ Wagg, const float* __restrict__ bagg,
           const float* __restrict__ Wmu,  const float* __restrict__ bmu,
           const float* __restrict__ Wvar, const float* __restrict__ bvar,
           float* __restrict__ out)
{
    __shared__ float sh_g[GAUX * 1024];
    __shared__ float sh_lat[GAUX * D];
    const int c  = threadIdx.x;
    const int g0 = blockIdx.x * GAUX;

    {
        const float4* src = (const float4*)(g_gbuf + g0 * 1024);
        float4* dst = (float4*)sh_g;
        #pragma unroll
        for (int i = 0; i < GAUX * 1024 / 4 / 256; i++)
            dst[i * 256 + c] = src[i * 256 + c];
    }
    __syncthreads();

    float lat[GAUX];
    {
        float bg = bagg[c];
        #pragma unroll
        for (int i = 0; i < GAUX; i++) lat[i] = bg;
    }
    for (int k4 = 0; k4 < 4 * D; k4 += 4) {
        float w0 = Wagg[(k4 + 0) * D + c];
        float w1 = Wagg[(k4 + 1) * D + c];
        float w2 = Wagg[(k4 + 2) * D + c];
        float w3 = Wagg[(k4 + 3) * D + c];
        #pragma unroll
        for (int i = 0; i < GAUX; i++) {
            float4 gv = *(const float4*)(sh_g + i * 1024 + k4);
            lat[i] = fmaf(gv.x, w0, fmaf(gv.y, w1, fmaf(gv.z, w2, fmaf(gv.w, w3, lat[i]))));
        }
    }
    __syncthreads();
    #pragma unroll
    for (int i = 0; i < GAUX; i++) sh_lat[i * D + c] = lat[i];
    __syncthreads();

    float mu[GAUX], lv[GAUX];
    {
        float bm_ = bmu[c], bv_ = bvar[c];
        #pragma unroll
        for (int i = 0; i < GAUX; i++) { mu[i] = bm_; lv[i] = bv_; }
    }
    for (int j4 = 0; j4 < D; j4 += 4) {
        float m0 = Wmu[(j4 + 0) * D + c],  m1 = Wmu[(j4 + 1) * D + c];
        float m2 = Wmu[(j4 + 2) * D + c],  m3 = Wmu[(j4 + 3) * D + c];
        float v0 = Wvar[(j4 + 0) * D + c], v1 = Wvar[(j4 + 1) * D + c];
        float v2 = Wvar[(j4 + 2) * D + c], v3 = Wvar[(j4 + 3) * D + c];
        #pragma unroll
        for (int i = 0; i < GAUX; i++) {
            float4 L = *(const float4*)(sh_lat + i * D + j4);
            mu[i] = fmaf(L.x, m0, fmaf(L.y, m1, fmaf(L.z, m2, fmaf(L.w, m3, mu[i]))));
            lv[i] = fmaf(L.x, v0, fmaf(L.y, v1, fmaf(L.z, v2, fmaf(L.w, v3, lv[i]))));
        }
    }
    #pragma unroll
    for (int i = 0; i < GAUX; i++) {
        out[(g0 + i) * D + c]          = mu[i];
        out[BG * D + (g0 + i) * D + c] = lv[i];
    }
}

// ---------------------------------------------------------------------------
extern "C" void kernel_launch(void* const* d_in, const int* in_sizes, int n_in,
                              void* d_out, int out_size)
{
    const float* geometry = (const float*)d_in[0];
    const int*   semantic = (const int*)d_in[1];
    const int*   eidx     = (const int*)d_in[2];
    const float* Wgeo = (const float*)d_in[4];
    const float* bgeo = (const float*)d_in[5];
    const float* emb  = (const float*)d_in[6];
    const float* Wlot = (const float*)d_in[7];
    const float* blot = (const float*)d_in[8];
    const float* Wmp1 = (const float*)d_in[9];
    const float* bmp1 = (const float*)d_in[10];
    const float* Wmp2 = (const float*)d_in[11];
    const float* bmp2 = (const float*)d_in[12];
    const float* Wmp3 = (const float*)d_in[13];
    const float* bmp3 = (const float*)d_in[14];
    const float* Wagg = (const float*)d_in[15];
    const float* bagg = (const float*)d_in[16];
    const float* Wmu  = (const float*)d_in[17];
    const float* bmu  = (const float*)d_in[18];
    const float* Wvar = (const float*)d_in[19];
    const float* bvar = (const float*)d_in[20];

    const int n_edges = in_sizes[2] / 2;
    const int* e_src = eidx;
    const int* e_dst = eidx + n_edges;

    // 17 fold + 384 Bfrag + 192 Wp2 blocks
    init_kernel<<<17 + 384 + 192, 256>>>(Wgeo, bgeo, emb, Wlot, blot,
                                         Wmp1, Wmp2, Wmp3);

    cudaFuncSetAttribute(graph_kernel, cudaFuncAttributeMaxDynamicSharedMemorySize,
                         DYN_SZ);
    graph_kernel<<<BG, 256, DYN_SZ>>>(
        geometry, semantic, e_src, e_dst, Wlot, bmp1, bmp2, bmp3);

    aux_kernel<<<BG / GAUX, 256>>>(Wagg, bagg, Wmu, bmu, Wvar, bvar, (float*)d_out);
}